// round 6
// baseline (speedup 1.0000x reference)
#include <cuda_runtime.h>
#include <cuda_bf16.h>
#include <cstdint>

// HMM forward: T=1024, S=512, D=32, K=64
// Emission: raw p = exp2(scaled quad) via packed f32x2 FMA (4-buffer ring, FIXED
//           task-4 refill). Recursion: 2-warp team per sequence, A in registers,
//           full-K d-sum via add2 register tree, single-stale scaling with exact
//           log2 telescoping. Scalar reduction fused into recursion (last block).

#define HT 1024
#define HS 512
#define HD 32
#define HK 64
#define LOG2PI_F 1.8378770664093453f
#define NEG_HALF_LOG2E -0.72134752044448169f
#define LN2_F 0.69314718055994531f

typedef unsigned long long ull;

__device__ float  g_P[(size_t)HT * HS * HK];   // 128 MB raw emission probs [t][s][k]
__device__ float4 g_W4[16 * HK];
__device__ float  g_C[HK];
__device__ float  g_loglik[HS];
__device__ unsigned int g_done;

__device__ __forceinline__ void fma2(ull& d, ull a, ull b, ull c) {
    asm("fma.rn.f32x2 %0, %1, %2, %3;" : "=l"(d) : "l"(a), "l"(b), "l"(c));
}
__device__ __forceinline__ void add2(ull& d, ull a, ull b) {
    asm("add.rn.f32x2 %0, %1, %2;" : "=l"(d) : "l"(a), "l"(b));
}
__device__ __forceinline__ ull pk2(float lo, float hi) {
    ull r;
    asm("mov.b64 %0, {%1, %2};" : "=l"(r) : "f"(lo), "f"(hi));
    return r;
}
__device__ __forceinline__ void unpk2(float& lo, float& hi, ull v) {
    asm("mov.b64 {%0, %1}, %2;" : "=f"(lo), "=f"(hi) : "l"(v));
}
__device__ __forceinline__ float ex2a(float x) {
    float r; asm("ex2.approx.f32 %0, %1;" : "=f"(r) : "f"(x)); return r;
}
__device__ __forceinline__ float lg2a(float x) {
    float r; asm("lg2.approx.f32 %0, %1;" : "=f"(r) : "f"(x)); return r;
}
__device__ __forceinline__ float rcpa(float x) {
    float r; asm("rcp.approx.f32 %0, %1;" : "=f"(r) : "f"(x)); return r;
}
__device__ __forceinline__ void barsync(int id, int cnt) {
    asm volatile("bar.sync %0, %1;" :: "r"(id), "r"(cnt) : "memory");
}

// -------- prep: per-state coefficients prescaled by -log2(e)/2; reset counter --------
__global__ void hmm_prep(const float* __restrict__ means, const float* __restrict__ covars) {
    int k = threadIdx.x;
    if (k == 0) g_done = 0;
    if (k >= HK) return;
    float c = (float)HD * LOG2PI_F;
    #pragma unroll
    for (int g = 0; g < 16; ++g) {
        int d0 = 2 * g, d1 = 2 * g + 1;
        float cv0 = covars[k * HD + d0], cv1 = covars[k * HD + d1];
        float mu0 = means [k * HD + d0], mu1 = means [k * HD + d1];
        float iv0 = 1.0f / cv0, iv1 = 1.0f / cv1;
        c += mu0 * mu0 * iv0 + logf(cv0);
        c += mu1 * mu1 * iv1 + logf(cv1);
        float4 v;
        v.x = NEG_HALF_LOG2E * iv0;
        v.y = NEG_HALF_LOG2E * iv1;
        v.z = NEG_HALF_LOG2E * (-2.0f * mu0 * iv0);
        v.w = NEG_HALF_LOG2E * (-2.0f * mu1 * iv1);
        g_W4[g * HK + k] = v;
    }
    g_C[k] = NEG_HALF_LOG2E * c;
}

// -------- emission: warp per (t,s) row; lane -> states (2l, 2l+1) --------
#define EM_CTAS 4096
#define EM_THREADS 128
#define EM_TPW 32

__global__ void __launch_bounds__(EM_THREADS, 2) hmm_emission(const float* __restrict__ data) {
    __shared__ __align__(16) float sx[4][4][HD];
    int lane = threadIdx.x & 31;
    int wid  = threadIdx.x >> 5;
    int gw   = blockIdx.x * (EM_THREADS / 32) + wid;
    int ts0  = gw * EM_TPW;

    int kA = 2 * lane, kB = 2 * lane + 1;
    ull w1A[16], w2A[16], w1B[16], w2B[16];
    #pragma unroll
    for (int g = 0; g < 16; ++g) {
        float4 a = g_W4[g * HK + kA];
        float4 b = g_W4[g * HK + kB];
        w1A[g] = pk2(a.x, a.y); w2A[g] = pk2(a.z, a.w);
        w1B[g] = pk2(b.x, b.y); w2B[g] = pk2(b.z, b.w);
    }
    float cA = g_C[kA], cB = g_C[kB];

    // ring invariant: task m lives in xr[m & 3]
    float xr[4];
    #pragma unroll
    for (int j = 0; j < 4; ++j)
        xr[j] = __ldg(&data[(size_t)(ts0 + j) * HD + lane]);

    sx[wid][0][lane] = xr[0];                                   // store task 0
    xr[0] = __ldg(&data[(size_t)(ts0 + 4) * HD + lane]);        // FIX: refill slot 0 with task 4
    __syncwarp();

    ull* Pout = reinterpret_cast<ull*>(g_P);

    for (int i = 0; i < EM_TPW; ++i) {
        int ts = ts0 + i;
        if (i + 1 < EM_TPW)
            sx[wid][(i + 1) & 3][lane] = xr[(i + 1) & 3];       // store task i+1
        if (i + 5 < EM_TPW)
            xr[(i + 1) & 3] = __ldg(&data[(size_t)(ts + 5) * HD + lane]);  // refill task i+5
        __syncwarp();
        const ull* xb = reinterpret_cast<const ull*>(sx[wid][i & 3]);
        ull aA0 = 0ULL, aA1 = 0ULL, aB0 = 0ULL, aB1 = 0ULL;
        #pragma unroll
        for (int g = 0; g < 8; ++g) {
            ull x2 = xb[g];
            ull tA, tB;
            fma2(tA, x2, w1A[g], w2A[g]);
            fma2(aA0, x2, tA, aA0);
            fma2(tB, x2, w1B[g], w2B[g]);
            fma2(aB0, x2, tB, aB0);
        }
        #pragma unroll
        for (int g = 8; g < 16; ++g) {
            ull x2 = xb[g];
            ull tA, tB;
            fma2(tA, x2, w1A[g], w2A[g]);
            fma2(aA1, x2, tA, aA1);
            fma2(tB, x2, w1B[g], w2B[g]);
            fma2(aB1, x2, tB, aB1);
        }
        ull sA, sB;
        add2(sA, aA0, aA1);
        add2(sB, aB0, aB1);
        float qa0, qa1, qb0, qb1;
        unpk2(qa0, qa1, sA);
        unpk2(qb0, qb1, sB);
        float pa = ex2a((qa0 + qa1) + cA);
        float pb = ex2a((qb0 + qb1) + cB);
        Pout[(size_t)ts * 32 + lane] = pk2(pa, pb);
    }
}

// -------- recursion: 2-warp team per sequence; lane -> output state h*32+lane --------
#define RC_TEAMS 4
#define RC_BLOCKS (HS / RC_TEAMS)
__global__ void __launch_bounds__(256, 1) hmm_recursion(const float* __restrict__ trans,
                                                        const float* __restrict__ initp,
                                                        float* __restrict__ alpha_out,
                                                        int write_alpha,
                                                        float* __restrict__ scal) {
    __shared__ __align__(16) float sv[RC_TEAMS][2][HK];
    int lane = threadIdx.x & 31;
    int wid  = threadIdx.x >> 5;
    int team = wid >> 1;
    int h    = wid & 1;
    int barid = team + 1;
    int s = blockIdx.x * RC_TEAMS + team;
    int k = h * 32 + lane;

    ull Ak[32];
    #pragma unroll
    for (int j = 0; j < 32; ++j)
        Ak[j] = pk2(__ldg(&trans[(2 * j) * HK + k]), __ldg(&trans[(2 * j + 1) * HK + k]));

    const float* P = g_P;
    const int soff = s * HK + k;
    const int tstr = HS * HK;

    float u = __ldg(&initp[k]) * __ldg(&P[soff]);
    sv[team][0][k] = u;
    float L = 0.0f;

    float pp[4];
    #pragma unroll
    for (int j = 0; j < 4; ++j)
        pp[j] = __ldg(&P[(size_t)(1 + j) * tstr + soff]);

    for (int t = 1; t < HT; ++t) {
        barsync(barid, 64);
        const ull* vb = reinterpret_cast<const ull*>(sv[team][(t - 1) & 1]);
        ull v[32];
        #pragma unroll
        for (int j = 0; j < 32; ++j) v[j] = vb[j];

        // d_{t-1}: full-K add2 tree (31 add2), overlaps matvec
        ull r0, r1, r2, r3, r4, r5, r6, r7;
        add2(r0, v[0],  v[1]);  add2(r1, v[2],  v[3]);
        add2(r2, v[4],  v[5]);  add2(r3, v[6],  v[7]);
        add2(r4, v[8],  v[9]);  add2(r5, v[10], v[11]);
        add2(r6, v[12], v[13]); add2(r7, v[14], v[15]);
        add2(r0, r0, r1); add2(r2, r2, r3); add2(r4, r4, r5); add2(r6, r6, r7);
        add2(r0, r0, r2); add2(r4, r4, r6);
        add2(r0, r0, r4);
        ull q0, q1, q2, q3, q4, q5, q6, q7;
        add2(q0, v[16], v[17]); add2(q1, v[18], v[19]);
        add2(q2, v[20], v[21]); add2(q3, v[22], v[23]);
        add2(q4, v[24], v[25]); add2(q5, v[26], v[27]);
        add2(q6, v[28], v[29]); add2(q7, v[30], v[31]);
        add2(q0, q0, q1); add2(q2, q2, q3); add2(q4, q4, q5); add2(q6, q6, q7);
        add2(q0, q0, q2); add2(q4, q4, q6);
        add2(q0, q0, q4);
        add2(r0, r0, q0);
        float dl, dh;
        unpk2(dl, dh, r0);
        float d = dl + dh;
        float rinv = rcpa(d);
        float lnd  = lg2a(d);

        // matvec: 4 chains of 8
        ull a0 = 0ULL, a1 = 0ULL, a2 = 0ULL, a3 = 0ULL;
        #pragma unroll
        for (int j = 0; j < 8; ++j)   fma2(a0, v[j], Ak[j], a0);
        #pragma unroll
        for (int j = 8; j < 16; ++j)  fma2(a1, v[j], Ak[j], a1);
        #pragma unroll
        for (int j = 16; j < 24; ++j) fma2(a2, v[j], Ak[j], a2);
        #pragma unroll
        for (int j = 24; j < 32; ++j) fma2(a3, v[j], Ak[j], a3);
        add2(a0, a0, a1);
        add2(a2, a2, a3);
        add2(a0, a0, a2);
        float ml, mh;
        unpk2(ml, mh, a0);
        float mv = ml + mh;

        float pr = pp[(t - 1) & 3] * rinv;
        if (t + 4 < HT)
            pp[(t - 1) & 3] = __ldg(&P[(size_t)(t + 4) * tstr + soff]);

        u = mv * pr;
        sv[team][t & 1][k] = u;
        L += lnd;
    }

    barsync(barid, 64);
    // final d_T: full-K sum
    {
        const ull* vb = reinterpret_cast<const ull*>(sv[team][(HT - 1) & 1]);
        ull f0;
        add2(f0, vb[0], vb[1]);
        #pragma unroll
        for (int j = 2; j < 32; ++j) { ull fv = vb[j]; add2(f0, f0, fv); }
        float fl, fh;
        unpk2(fl, fh, f0);
        float dT = fl + fh;

        if (write_alpha)
            alpha_out[soff] = u * rcpa(dT);
        if (k == 0)
            g_loglik[s] = L + lg2a(dT);
    }

    // fused finalize: release fence -> counter -> acquire fence -> last block reduces
    __threadfence();
    __syncthreads();
    __shared__ unsigned int amlast;
    if (threadIdx.x == 0)
        amlast = atomicAdd(&g_done, 1u);
    __syncthreads();
    if (amlast == RC_BLOCKS - 1 && scal != nullptr) {
        __threadfence();
        __shared__ float red[256];
        int tid = threadIdx.x;
        float acc = g_loglik[tid] + g_loglik[tid + 256];
        red[tid] = acc;
        __syncthreads();
        for (int st = 128; st > 0; st >>= 1) {
            if (tid < st) red[tid] += red[tid + st];
            __syncthreads();
        }
        if (tid == 0) scal[0] = -red[0] * LN2_F;
    }
}

extern "C" void kernel_launch(void* const* d_in, const int* in_sizes, int n_in,
                              void* d_out, int out_size) {
    const float* data   = (const float*)d_in[0];
    const float* initp  = (const float*)d_in[1];
    const float* trans  = (const float*)d_in[2];
    const float* means  = (const float*)d_in[3];
    const float* covars = (const float*)d_in[4];
    float* out = (float*)d_out;

    hmm_prep<<<1, 64>>>(means, covars);
    hmm_emission<<<EM_CTAS, EM_THREADS>>>(data);

    const int AK = HS * HK;  // 32768
    int write_alpha = (out_size >= AK) ? 1 : 0;
    float* scal = nullptr;
    if (out_size == 1)       scal = out;
    else if (out_size > AK)  scal = out + AK;

    hmm_recursion<<<RC_BLOCKS, 256>>>(trans, initp, out, write_alpha, scal);
}